// round 1
// baseline (speedup 1.0000x reference)
#include <cuda_runtime.h>
#include <cstdint>

// Problem constants (fixed by the reference: B=4, N=262144, G=128)
#define NBATCH 4
#define NPART  262144          // 2^18
#define GDIM   128
#define BOUNDC 3

__constant__ float kDT = 5e-4f;

// Fused grid_op + g2p:
//   grid_op is pointwise per grid node, so instead of materializing the
//   transformed 100 MB grid, each particle applies the friction/clamp math
//   to the 27 nodes it gathers. Saves ~200 MB of DRAM traffic.
__global__ __launch_bounds__(256)
void fused_g2p_kernel(const float* __restrict__ x,
                      const float* __restrict__ friction,
                      const float* __restrict__ pred,
                      const float* __restrict__ collider_floor,
                      const int*   __restrict__ statics,
                      float* __restrict__ out)
{
    const int pid = blockIdx.x * blockDim.x + threadIdx.x;
    const int total = NBATCH * NPART;
    if (pid >= total) return;

    const int b = pid >> 18;               // pid / NPART
    const float dx = 1.0f / (float)GDIM;
    const float inv_dx = (float)GDIM;

    // Particle position
    const float x0 = x[pid * 3 + 0];
    const float x1 = x[pid * 3 + 1];
    const float x2 = x[pid * 3 + 2];

    const float mu      = friction[b];
    const float floor_y = collider_floor[b];
    const float floor_thr = floor_y + (float)BOUNDC * dx;   // near-floor threshold

    // Per-axis base index, fractional offset, quadratic B-spline weights
    float w0[3], w1[3], w2[3];
    int   i0[3], i1[3], i2[3];
    int   bx, by, bz;
    {
        const float p0 = x0 * inv_dx;
        const float p1 = x1 * inv_dx;
        const float p2 = x2 * inv_dx;
        bx = (int)floorf(p0 - 0.5f);
        by = (int)floorf(p1 - 0.5f);
        bz = (int)floorf(p2 - 0.5f);
        const float f0 = p0 - (float)bx;
        const float f1 = p1 - (float)by;
        const float f2 = p2 - (float)bz;

        w0[0] = 0.5f * (1.5f - f0) * (1.5f - f0);
        w0[1] = 0.75f - (f0 - 1.0f) * (f0 - 1.0f);
        w0[2] = 0.5f * (f0 - 0.5f) * (f0 - 0.5f);
        w1[0] = 0.5f * (1.5f - f1) * (1.5f - f1);
        w1[1] = 0.75f - (f1 - 1.0f) * (f1 - 1.0f);
        w1[2] = 0.5f * (f1 - 0.5f) * (f1 - 0.5f);
        w2[0] = 0.5f * (1.5f - f2) * (1.5f - f2);
        w2[1] = 0.75f - (f2 - 1.0f) * (f2 - 1.0f);
        w2[2] = 0.5f * (f2 - 0.5f) * (f2 - 0.5f);

        #pragma unroll
        for (int c = 0; c < 3; c++) {
            i0[c] = min(max(bx + c, 0), GDIM - 1);
            i1[c] = min(max(by + c, 0), GDIM - 1);
            i2[c] = min(max(bz + c, 0), GDIM - 1);
        }
    }

    const float* __restrict__ gbase =
        pred + (size_t)b * (size_t)(GDIM * GDIM * GDIM * 3);

    float accx = 0.0f, accy = 0.0f, accz = 0.0f;

    #pragma unroll
    for (int i = 0; i < 3; i++) {
        const int gi = i0[i];
        const bool xlow  = gi < BOUNDC;
        const bool xhigh = gi >= GDIM - BOUNDC;
        const float* __restrict__ plane = gbase + (size_t)gi * (GDIM * GDIM * 3);
        #pragma unroll
        for (int j = 0; j < 3; j++) {
            const int gj = i1[j];
            const float wij = w0[i] * w1[j];
            const bool nearf = ((float)gj * dx) <= floor_thr;
            const bool ylow  = gj < BOUNDC;
            const bool yhigh = gj >= GDIM - BOUNDC;
            const float* __restrict__ row = plane + gj * (GDIM * 3);
            #pragma unroll
            for (int k = 0; k < 3; k++) {
                const int gk = i2[k];
                const float* __restrict__ p = row + gk * 3;
                float vx_ = p[0];
                float vy_ = p[1];
                float vz_ = p[2];

                // --- grid_op: floor Coulomb friction (normal = +y) ---
                if (nearf && vy_ < 0.0f) {
                    const float vtn = sqrtf(vx_ * vx_ + vz_ * vz_ + 1e-10f);
                    const float s = fmaxf(0.0f, 1.0f + mu * vy_ / vtn);
                    vx_ *= s;
                    vz_ *= s;
                    vy_ = 0.0f;
                }
                // --- grid_op: domain boundary band clamp ---
                if ((xlow && vx_ < 0.0f) || (xhigh && vx_ > 0.0f)) vx_ = 0.0f;
                if ((ylow && vy_ < 0.0f) || (yhigh && vy_ > 0.0f)) vy_ = 0.0f;
                const bool zlow  = gk < BOUNDC;
                const bool zhigh = gk >= GDIM - BOUNDC;
                if ((zlow && vz_ < 0.0f) || (zhigh && vz_ > 0.0f)) vz_ = 0.0f;

                const float w = wij * w2[k];
                accx = fmaf(w, vx_, accx);
                accy = fmaf(w, vy_, accy);
                accz = fmaf(w, vz_, accz);
            }
        }
    }

    const float m = (float)statics[pid];
    accx *= m;
    accy *= m;
    accz *= m;

    // Outputs: x_next in out[0 : total*3], v_next in out[total*3 : 2*total*3]
    float* __restrict__ out_x = out;
    float* __restrict__ out_v = out + (size_t)total * 3;

    out_x[pid * 3 + 0] = fmaf(kDT, accx, x0);
    out_x[pid * 3 + 1] = fmaf(kDT, accy, x1);
    out_x[pid * 3 + 2] = fmaf(kDT, accz, x2);
    out_v[pid * 3 + 0] = accx;
    out_v[pid * 3 + 1] = accy;
    out_v[pid * 3 + 2] = accz;
}

extern "C" void kernel_launch(void* const* d_in, const int* in_sizes, int n_in,
                              void* d_out, int out_size)
{
    // metadata order: x, v, friction, pred, collider_floor, statics_enabled, step
    const float* x              = (const float*)d_in[0];
    // d_in[1] = v (unused by the reference computation)
    const float* friction       = (const float*)d_in[2];
    const float* pred           = (const float*)d_in[3];
    const float* collider_floor = (const float*)d_in[4];
    const int*   statics        = (const int*)d_in[5];
    // d_in[6] = step (unused)

    float* out = (float*)d_out;

    const int total = NBATCH * NPART;
    const int threads = 256;
    const int blocks = (total + threads - 1) / threads;
    fused_g2p_kernel<<<blocks, threads>>>(x, friction, pred, collider_floor,
                                          statics, out);
}

// round 2
// speedup vs baseline: 1.0380x; 1.0380x over previous
#include <cuda_runtime.h>
#include <cstdint>

// Problem constants (fixed by the reference: B=4, N=262144, G=128)
#define NBATCH 4
#define NPART  262144          // 2^18
#define GDIM   128
#define BOUNDC 3
#define NNODE  (NBATCH * GDIM * GDIM * GDIM)   // 8388608

__constant__ float kDT = 5e-4f;

// Scratch: grid_op output as float4-per-node so every g2p gather is ONE
// aligned LDG.128 instead of 3 scattered LDG.32. 134 MB static scratch.
__device__ float4 g_grid[NNODE];

// ---------------------------------------------------------------------------
// Phase 1: pointwise grid_op (floor Coulomb friction + boundary clamp),
// applied ONCE per node, written as padded float4. Each thread handles 4
// consecutive nodes = 3 aligned float4 reads + 4 float4 writes (coalesced).
// ---------------------------------------------------------------------------
__global__ __launch_bounds__(256)
void grid_op_kernel(const float* __restrict__ pred,
                    const float* __restrict__ friction,
                    const float* __restrict__ collider_floor)
{
    const int t = blockIdx.x * blockDim.x + threadIdx.x;   // nodes 4t..4t+3
    if (t >= NNODE / 4) return;

    const float4* __restrict__ p4 = (const float4*)pred;
    const float4 A = p4[3 * t + 0];
    const float4 Bv = p4[3 * t + 1];
    const float4 C = p4[3 * t + 2];

    float vx[4] = {A.x, A.w, Bv.z, C.y};
    float vy[4] = {A.y, Bv.x, Bv.w, C.z};
    float vz[4] = {A.z, Bv.y, C.x, C.w};

    const int n0  = 4 * t;
    const int b   = n0 >> 21;
    const int gi  = (n0 >> 14) & 127;
    const int gj  = (n0 >> 7) & 127;
    const int gk0 = n0 & 127;      // multiple of 4: the 4 nodes share b,gi,gj

    const float dx  = 1.0f / (float)GDIM;
    const float mu  = friction[b];
    const float thr = collider_floor[b] + (float)BOUNDC * dx;

    const bool nearf = ((float)gj * dx) <= thr;
    const bool xlow  = gi < BOUNDC,         xhigh = gi >= GDIM - BOUNDC;
    const bool ylow  = gj < BOUNDC,         yhigh = gj >= GDIM - BOUNDC;

    float4 outv[4];
    #pragma unroll
    for (int s = 0; s < 4; s++) {
        float X = vx[s], Y = vy[s], Z = vz[s];
        // floor Coulomb friction (normal = +y)
        if (nearf && Y < 0.0f) {
            const float vtn = sqrtf(X * X + Z * Z + 1e-10f);
            const float sc = fmaxf(0.0f, 1.0f + mu * Y / vtn);
            X *= sc; Z *= sc; Y = 0.0f;
        }
        // boundary band clamps
        if ((xlow && X < 0.0f) || (xhigh && X > 0.0f)) X = 0.0f;
        if ((ylow && Y < 0.0f) || (yhigh && Y > 0.0f)) Y = 0.0f;
        const int gk = gk0 + s;
        if ((gk < BOUNDC && Z < 0.0f) || (gk >= GDIM - BOUNDC && Z > 0.0f)) Z = 0.0f;
        outv[s] = make_float4(X, Y, Z, 0.0f);
    }

    #pragma unroll
    for (int s = 0; s < 4; s++) g_grid[n0 + s] = outv[s];
}

// ---------------------------------------------------------------------------
// Phase 2: g2p gather — 27 single LDG.128 gathers per particle.
// ---------------------------------------------------------------------------
__global__ __launch_bounds__(256)
void g2p_kernel(const float* __restrict__ x,
                const int*   __restrict__ statics,
                float* __restrict__ out)
{
    const int pid = blockIdx.x * blockDim.x + threadIdx.x;
    const int total = NBATCH * NPART;
    if (pid >= total) return;

    const int b = pid >> 18;
    const float inv_dx = (float)GDIM;

    const float x0 = x[pid * 3 + 0];
    const float x1 = x[pid * 3 + 1];
    const float x2 = x[pid * 3 + 2];

    float w0[3], w1[3], w2[3];
    int   i0[3], i1[3], i2[3];
    {
        const float p0 = x0 * inv_dx;
        const float p1 = x1 * inv_dx;
        const float p2 = x2 * inv_dx;
        const int bx = (int)floorf(p0 - 0.5f);
        const int by = (int)floorf(p1 - 0.5f);
        const int bz = (int)floorf(p2 - 0.5f);
        const float f0 = p0 - (float)bx;
        const float f1 = p1 - (float)by;
        const float f2 = p2 - (float)bz;

        w0[0] = 0.5f * (1.5f - f0) * (1.5f - f0);
        w0[1] = 0.75f - (f0 - 1.0f) * (f0 - 1.0f);
        w0[2] = 0.5f * (f0 - 0.5f) * (f0 - 0.5f);
        w1[0] = 0.5f * (1.5f - f1) * (1.5f - f1);
        w1[1] = 0.75f - (f1 - 1.0f) * (f1 - 1.0f);
        w1[2] = 0.5f * (f1 - 0.5f) * (f1 - 0.5f);
        w2[0] = 0.5f * (1.5f - f2) * (1.5f - f2);
        w2[1] = 0.75f - (f2 - 1.0f) * (f2 - 1.0f);
        w2[2] = 0.5f * (f2 - 0.5f) * (f2 - 0.5f);

        #pragma unroll
        for (int c = 0; c < 3; c++) {
            i0[c] = min(max(bx + c, 0), GDIM - 1);
            i1[c] = min(max(by + c, 0), GDIM - 1);
            i2[c] = min(max(bz + c, 0), GDIM - 1);
        }
    }

    const float4* __restrict__ g = g_grid + (size_t)b * (GDIM * GDIM * GDIM);

    float accx = 0.0f, accy = 0.0f, accz = 0.0f;

    #pragma unroll
    for (int i = 0; i < 3; i++) {
        const float4* __restrict__ plane = g + (size_t)i0[i] * (GDIM * GDIM);
        #pragma unroll
        for (int j = 0; j < 3; j++) {
            const float4* __restrict__ row = plane + i1[j] * GDIM;
            const float wij = w0[i] * w1[j];
            #pragma unroll
            for (int k = 0; k < 3; k++) {
                const float4 v = __ldg(row + i2[k]);
                const float w = wij * w2[k];
                accx = fmaf(w, v.x, accx);
                accy = fmaf(w, v.y, accy);
                accz = fmaf(w, v.z, accz);
            }
        }
    }

    const float m = (float)statics[pid];
    accx *= m; accy *= m; accz *= m;

    float* __restrict__ out_x = out;
    float* __restrict__ out_v = out + (size_t)total * 3;

    out_x[pid * 3 + 0] = fmaf(kDT, accx, x0);
    out_x[pid * 3 + 1] = fmaf(kDT, accy, x1);
    out_x[pid * 3 + 2] = fmaf(kDT, accz, x2);
    out_v[pid * 3 + 0] = accx;
    out_v[pid * 3 + 1] = accy;
    out_v[pid * 3 + 2] = accz;
}

extern "C" void kernel_launch(void* const* d_in, const int* in_sizes, int n_in,
                              void* d_out, int out_size)
{
    // metadata order: x, v, friction, pred, collider_floor, statics_enabled, step
    const float* x              = (const float*)d_in[0];
    const float* friction       = (const float*)d_in[2];
    const float* pred           = (const float*)d_in[3];
    const float* collider_floor = (const float*)d_in[4];
    const int*   statics        = (const int*)d_in[5];

    float* out = (float*)d_out;

    const int threads = 256;
    grid_op_kernel<<<(NNODE / 4 + threads - 1) / threads, threads>>>(
        pred, friction, collider_floor);

    const int total = NBATCH * NPART;
    g2p_kernel<<<(total + threads - 1) / threads, threads>>>(x, statics, out);
}

// round 3
// speedup vs baseline: 1.5114x; 1.4560x over previous
#include <cuda_runtime.h>
#include <cstdint>

// Problem constants (fixed by the reference: B=4, N=262144, G=128)
#define NBATCH 4
#define NPART  262144          // 2^18
#define GDIM   128
#define BOUNDC 3

__constant__ float kDT = 5e-4f;

// Fully fused grid_op + g2p, zero scratch traffic.
// Each z-row of 3 nodes (9 floats, 36B at 4B-aligned f*4, f = 3*(row*128+s))
// is fetched with 3 aligned LDG.128 covering a 48B window; since r = f&3 <= 3
// the 9 floats always fit. r = (3s)&3 is uniform per particle, so extraction
// is a cheap 2-predicate SEL tree.
__global__ __launch_bounds__(256)
void fused_kernel(const float* __restrict__ x,
                  const float* __restrict__ friction,
                  const float* __restrict__ pred,
                  const float* __restrict__ collider_floor,
                  const int*   __restrict__ statics,
                  float* __restrict__ out)
{
    const int pid = blockIdx.x * blockDim.x + threadIdx.x;
    const int total = NBATCH * NPART;
    if (pid >= total) return;

    const int b = pid >> 18;
    const float dx = 1.0f / (float)GDIM;
    const float inv_dx = (float)GDIM;

    const float x0 = x[pid * 3 + 0];
    const float x1 = x[pid * 3 + 1];
    const float x2 = x[pid * 3 + 2];

    const float mu  = friction[b];
    const float thr = collider_floor[b] + (float)BOUNDC * dx;

    // ---- stencil setup ----
    float w0[3], w1[3], w2[3];
    int   i0[3], i1[3];
    int   s;            // clamped z-row start (3 consecutive nodes s,s+1,s+2)
    float Wz[3];        // z weights redistributed onto nodes s..s+2
    {
        const float p0f = x0 * inv_dx;
        const float p1f = x1 * inv_dx;
        const float p2f = x2 * inv_dx;
        const int bx = (int)floorf(p0f - 0.5f);
        const int by = (int)floorf(p1f - 0.5f);
        const int bz = (int)floorf(p2f - 0.5f);
        const float f0 = p0f - (float)bx;
        const float f1 = p1f - (float)by;
        const float f2 = p2f - (float)bz;

        w0[0] = 0.5f * (1.5f - f0) * (1.5f - f0);
        w0[1] = 0.75f - (f0 - 1.0f) * (f0 - 1.0f);
        w0[2] = 0.5f * (f0 - 0.5f) * (f0 - 0.5f);
        w1[0] = 0.5f * (1.5f - f1) * (1.5f - f1);
        w1[1] = 0.75f - (f1 - 1.0f) * (f1 - 1.0f);
        w1[2] = 0.5f * (f1 - 0.5f) * (f1 - 0.5f);
        w2[0] = 0.5f * (1.5f - f2) * (1.5f - f2);
        w2[1] = 0.75f - (f2 - 1.0f) * (f2 - 1.0f);
        w2[2] = 0.5f * (f2 - 0.5f) * (f2 - 0.5f);

        #pragma unroll
        for (int c = 0; c < 3; c++) {
            i0[c] = min(max(bx + c, 0), GDIM - 1);
            i1[c] = min(max(by + c, 0), GDIM - 1);
        }

        s = min(max(bz, 0), GDIM - 3);
        Wz[0] = 0.0f; Wz[1] = 0.0f; Wz[2] = 0.0f;
        #pragma unroll
        for (int k = 0; k < 3; k++) {
            const int idx = min(max(bz + k, 0), GDIM - 1) - s;   // 0..2
            #pragma unroll
            for (int t = 0; t < 3; t++)
                Wz[t] += (idx == t) ? w2[k] : 0.0f;
        }
    }

    const int s3 = 3 * s;
    const int r  = s3 & 3;             // uniform per particle
    const bool p0s = (r & 1) != 0;
    const bool p1s = (r & 2) != 0;
    const int sq = s3 >> 2;            // float4 sub-offset of the row window

    // z-clamp bools for the 3 physical nodes s, s+1, s+2
    bool zlow[3], zhigh[3];
    #pragma unroll
    for (int t = 0; t < 3; t++) {
        const int gk = s + t;
        zlow[t]  = gk < BOUNDC;
        zhigh[t] = gk >= GDIM - BOUNDC;
    }

    const float4* __restrict__ g4 =
        (const float4*)(pred) + (size_t)b * (GDIM * GDIM * GDIM * 3 / 4);

    float accx = 0.0f, accy = 0.0f, accz = 0.0f;

    #pragma unroll
    for (int i = 0; i < 3; i++) {
        const int gi = i0[i];
        const bool xlow  = gi < BOUNDC;
        const bool xhigh = gi >= GDIM - BOUNDC;
        #pragma unroll
        for (int j = 0; j < 3; j++) {
            const int gj = i1[j];
            const float wij = w0[i] * w1[j];
            const bool nearf = ((float)gj * dx) <= thr;
            const bool ylow  = gj < BOUNDC;
            const bool yhigh = gj >= GDIM - BOUNDC;

            // row window: floats f..f+8, f = (gi*128+gj)*384 + 3s
            const int f4 = (gi * GDIM + gj) * 96 + sq;
            const float4 q0 = __ldg(g4 + f4 + 0);
            const float4 q1 = __ldg(g4 + f4 + 1);
            const float4 q2 = __ldg(g4 + f4 + 2);

            const float wq[12] = {q0.x, q0.y, q0.z, q0.w,
                                  q1.x, q1.y, q1.z, q1.w,
                                  q2.x, q2.y, q2.z, q2.w};
            float v[9];
            #pragma unroll
            for (int t = 0; t < 9; t++) {
                const float a  = p0s ? wq[t + 1] : wq[t];
                const float bb = p0s ? wq[t + 3] : wq[t + 2];
                v[t] = p1s ? bb : a;
            }

            // grid_op + weighted accumulate for the 3 nodes of this row
            #pragma unroll
            for (int t = 0; t < 3; t++) {
                float vx_ = v[3 * t + 0];
                float vy_ = v[3 * t + 1];
                float vz_ = v[3 * t + 2];

                // floor Coulomb friction (normal = +y)
                if (nearf && vy_ < 0.0f) {
                    const float rinv = rsqrtf(vx_ * vx_ + vz_ * vz_ + 1e-10f);
                    const float sc = fmaxf(0.0f, fmaf(mu * vy_, rinv, 1.0f));
                    vx_ *= sc; vz_ *= sc; vy_ = 0.0f;
                }
                // boundary band clamps
                if ((xlow && vx_ < 0.0f) || (xhigh && vx_ > 0.0f)) vx_ = 0.0f;
                if ((ylow && vy_ < 0.0f) || (yhigh && vy_ > 0.0f)) vy_ = 0.0f;
                if ((zlow[t] && vz_ < 0.0f) || (zhigh[t] && vz_ > 0.0f)) vz_ = 0.0f;

                const float w = wij * Wz[t];
                accx = fmaf(w, vx_, accx);
                accy = fmaf(w, vy_, accy);
                accz = fmaf(w, vz_, accz);
            }
        }
    }

    const float m = (float)statics[pid];
    accx *= m; accy *= m; accz *= m;

    float* __restrict__ out_x = out;
    float* __restrict__ out_v = out + (size_t)total * 3;

    out_x[pid * 3 + 0] = fmaf(kDT, accx, x0);
    out_x[pid * 3 + 1] = fmaf(kDT, accy, x1);
    out_x[pid * 3 + 2] = fmaf(kDT, accz, x2);
    out_v[pid * 3 + 0] = accx;
    out_v[pid * 3 + 1] = accy;
    out_v[pid * 3 + 2] = accz;
}

extern "C" void kernel_launch(void* const* d_in, const int* in_sizes, int n_in,
                              void* d_out, int out_size)
{
    // metadata order: x, v, friction, pred, collider_floor, statics_enabled, step
    const float* x              = (const float*)d_in[0];
    const float* friction       = (const float*)d_in[2];
    const float* pred           = (const float*)d_in[3];
    const float* collider_floor = (const float*)d_in[4];
    const int*   statics        = (const int*)d_in[5];

    float* out = (float*)d_out;

    const int total = NBATCH * NPART;
    const int threads = 256;
    fused_kernel<<<(total + threads - 1) / threads, threads>>>(
        x, friction, pred, collider_floor, statics, out);
}